// round 14
// baseline (speedup 1.0000x reference)
#include <cuda_runtime.h>
#include <cuda_fp16.h>
#include <math.h>
#include <stdint.h>

// Problem constants
#define EN      200000
#define IND     128
#define HIDD    32
#define NH      4
#define OUTD    128
#define MAXK    16
#define TM      64                     // rows per block (attention kernel)
#define NBLK    (EN / TM)              // 3125
#define PTM     64                     // rows per tile (projection kernel)
#define PTILES  ((EN + PTM - 1) / PTM) // 3125
#define PHALF   148                    // blocks per projection type
#define SH      136                    // smem row stride in halfs (128 + 8 pad)

// Scratch (device globals; no allocation)
__device__ __half g_kv[(size_t)EN * 256];  // [e][0:128]=k (head-major), [128:256]=v
__device__ __half g_q [(size_t)EN * 128];  // q, head-major
__device__ __half g_g [(size_t)EN * 128];  // sigmoid gate, head-major
__device__ float  g_bh[(size_t)EN * NH];   // [e][h]
__device__ int    g_kstride;               // 2 if klist is int64, 1 if int32

// m16n8k16 f16 MMA, fp32 accum. A row-major frag, B col-major frag.
__device__ __forceinline__ void mma16816(float c[4], unsigned a0, unsigned a1,
                                         unsigned a2, unsigned a3,
                                         unsigned b0, unsigned b1)
{
    asm volatile(
        "mma.sync.aligned.m16n8k16.row.col.f32.f16.f16.f32 "
        "{%0,%1,%2,%3}, {%4,%5,%6,%7}, {%8,%9}, {%0,%1,%2,%3};\n"
        : "+f"(c[0]), "+f"(c[1]), "+f"(c[2]), "+f"(c[3])
        : "r"(a0), "r"(a1), "r"(a2), "r"(a3), "r"(b0), "r"(b1));
}

__device__ __forceinline__ unsigned ldh2(const __half* p) { return *(const unsigned*)p; }

// ---------------------------------------------------------------------------
// Kernel A: projections, split into two CTA flavors co-resident per SM.
// Even blocks: K,V -> g_kv (+ b tail, + klist detect on block 0).
// Odd  blocks: Q -> g_q, G (sigmoid) -> g_g.
// Each CTA: 512 threads, 2 weight matrices in smem (256 cols), double-
// buffered 64-row Z tiles. 296 blocks -> 2 CTAs/SM.
// ---------------------------------------------------------------------------
__global__ void __launch_bounds__(512, 2) kproj2(
    const float* __restrict__ Z,
    const float* __restrict__ Wk,
    const float* __restrict__ Wv,
    const float* __restrict__ Wq,
    const float* __restrict__ Wg,
    const float* __restrict__ Wb,
    const float* __restrict__ bgv,
    const int*   __restrict__ kw)
{
    extern __shared__ __half sh[];
    __half* sZ0 = sh;                         // [64][SH]
    __half* sZ1 = sh + PTM * SH;              // [64][SH]
    __half* sW  = sh + 2 * PTM * SH;          // [256][SH]
    __half* sWb = sh + 2 * PTM * SH + 256 * SH;  // [512]
    float*  sbg = (float*)(sWb + 512);        // [128]

    const int tid = threadIdx.x;
    const bool qg = (blockIdx.x & 1);         // 0: K,V   1: Q,G

    if (blockIdx.x == 0 && tid == 0) {
        int is64 = 1;
        for (int i = 0; i < 4096; i++) {
            int hi = kw[2 * i + 1];
            if (hi != 0 && hi != -1) { is64 = 0; break; }
        }
        g_kstride = is64 ? 2 : 1;
    }

    // Stage this flavor's two weight matrices (rows 0-127: Wk/Wq, 128-255: Wv/Wg)
    const float* W0 = qg ? Wq : Wk;
    const float* W1 = qg ? Wg : Wv;
    for (int i = tid; i < 256 * 32; i += 512) {
        int col = i >> 5, kq = i & 31;
        const float* src = (col < 128) ? (W0 + (size_t)col * IND)
                                       : (W1 + (size_t)(col - 128) * IND);
        float4 w = *(const float4*)(src + kq * 4);
        *(__half2*)&sW[col * SH + kq * 4]     = __floats2half2_rn(w.x, w.y);
        *(__half2*)&sW[col * SH + kq * 4 + 2] = __floats2half2_rn(w.z, w.w);
    }
    if (!qg) {
        for (int i = tid; i < NH * IND; i += 512) sWb[i] = __float2half_rn(Wb[i]);
    } else {
        for (int i = tid; i < 128; i += 512) sbg[i] = bgv[i];
    }

    const int lane = tid & 31, wid = tid >> 5;
    const int g = lane >> 2, tig = lane & 3;
    const int rb = (wid & 3) * 16;    // row band 0..48 (64 rows)
    const int cb = (wid >> 2) * 64;   // col band 0..192 (256 cols)

    // Tile loader (fp32 -> fp16), 64 rows
    auto load_tile = [&](int t, __half* dstZ) {
        const int row0 = t * PTM;
        for (int i = tid; i < PTM * 32; i += 512) {
            int r = i >> 5, c = i & 31;
            int rg = row0 + r; if (rg >= EN) rg = EN - 1;
            float4 v = *(const float4*)(Z + (size_t)rg * IND + c * 4);
            *(__half2*)&dstZ[r * SH + c * 4]     = __floats2half2_rn(v.x, v.y);
            *(__half2*)&dstZ[r * SH + c * 4 + 2] = __floats2half2_rn(v.z, v.w);
        }
    };

    int t = blockIdx.x >> 1;
    if (t < PTILES) load_tile(t, sZ0);
    __syncthreads();

    int buf = 0;
    for (; t < PTILES; t += PHALF) {
        __half* sZ  = buf ? sZ1 : sZ0;
        __half* sZn = buf ? sZ0 : sZ1;

        // Prefetch next tile into the other buffer (overlaps with MMA below)
        int tn = t + PHALF;
        if (tn < PTILES) load_tile(tn, sZn);

        const int row0 = t * PTM;
        const int r0g = row0 + rb + g;

        float acc[8][4] = {};
        #pragma unroll
        for (int k0 = 0; k0 < 8; k0++) {
            const __half* pa = sZ + (rb + g) * SH + k0 * 16 + tig * 2;
            unsigned a0 = ldh2(pa);
            unsigned a1 = ldh2(pa + 8 * SH);
            unsigned a2 = ldh2(pa + 8);
            unsigned a3 = ldh2(pa + 8 * SH + 8);
            #pragma unroll
            for (int nt = 0; nt < 8; nt++) {
                const __half* pb = sW + (cb + nt * 8 + g) * SH + k0 * 16 + tig * 2;
                mma16816(acc[nt], a0, a1, a2, a3, ldh2(pb), ldh2(pb + 8));
            }
        }

        if (!qg) {
            // cols 0..255 map directly into g_kv rows
            #pragma unroll
            for (int nt = 0; nt < 8; nt++) {
                int col = cb + nt * 8 + tig * 2;
                if (r0g < EN)
                    *(__half2*)&g_kv[(size_t)r0g * 256 + col] =
                        __floats2half2_rn(acc[nt][0], acc[nt][1]);
                if (r0g + 8 < EN)
                    *(__half2*)&g_kv[(size_t)(r0g + 8) * 256 + col] =
                        __floats2half2_rn(acc[nt][2], acc[nt][3]);
            }
            // b tail: 256 (row, head) dots
            if (tid < PTM * NH) {
                int r = tid >> 2, h = tid & 3;
                int rg = row0 + r;
                if (rg < EN) {
                    float s = 0.f;
                    #pragma unroll 8
                    for (int k = 0; k < 128; k += 2) {
                        float2 a = __half22float2(*(__half2*)&sZ[r * SH + k]);
                        float2 b = __half22float2(*(__half2*)&sWb[h * IND + k]);
                        s += a.x * b.x + a.y * b.y;
                    }
                    g_bh[(size_t)rg * NH + h] = s;
                }
            }
        } else {
            #pragma unroll
            for (int nt = 0; nt < 8; nt++) {
                int col = cb + nt * 8 + tig * 2;
                if (col < 128) {
                    if (r0g < EN)
                        *(__half2*)&g_q[(size_t)r0g * 128 + col] =
                            __floats2half2_rn(acc[nt][0], acc[nt][1]);
                    if (r0g + 8 < EN)
                        *(__half2*)&g_q[(size_t)(r0g + 8) * 128 + col] =
                            __floats2half2_rn(acc[nt][2], acc[nt][3]);
                } else {
                    int c2 = col - 128;
                    float g0 = 1.f / (1.f + __expf(-(acc[nt][0] + sbg[c2])));
                    float g1 = 1.f / (1.f + __expf(-(acc[nt][1] + sbg[c2 + 1])));
                    float g2 = 1.f / (1.f + __expf(-(acc[nt][2] + sbg[c2])));
                    float g3 = 1.f / (1.f + __expf(-(acc[nt][3] + sbg[c2 + 1])));
                    if (r0g < EN)
                        *(__half2*)&g_g[(size_t)r0g * 128 + c2] = __floats2half2_rn(g0, g1);
                    if (r0g + 8 < EN)
                        *(__half2*)&g_g[(size_t)(r0g + 8) * 128 + c2] = __floats2half2_rn(g2, g3);
                }
            }
        }

        __syncthreads();   // next-tile stores complete; current tile consumed
        buf ^= 1;
    }
}

// ---------------------------------------------------------------------------
// Kernel B: gather attention + gating + output GEMM. 512 threads, 64 rows.
// A thread PAIR handles one (row, head): p = tid&1 selects 16-dim half.
// Slot loop is branch-free so the pair shuffle never sees divergent lanes.
// ---------------------------------------------------------------------------
__global__ void __launch_bounds__(512, 2) katt_out(
    const int*   __restrict__ kw,
    const float* __restrict__ Wout,
    const float* __restrict__ bout,
    float*       __restrict__ out)
{
    extern __shared__ __half sh[];
    __half* sX  = sh;                          // [64][SH]  gated X (A operand)
    __half* sW  = sh + 64 * SH;                // [128][SH] Wout (B operand)
    int*    skl = (int*)(sh + 192 * SH);       // [64][32]
    float*  sbo = (float*)(skl + 2048);        // [128]

    const int tid  = threadIdx.x;
    const int row0 = blockIdx.x * TM;
    const int st   = g_kstride;

    // Stage Wout + bout + klist
    const float4* W4 = (const float4*)Wout;
    for (int i = tid; i < 128 * 32; i += 512) {
        int o = i >> 5, kq = i & 31;
        float4 w = W4[o * 32 + kq];
        *(__half2*)&sW[o * SH + kq * 4]     = __floats2half2_rn(w.x, w.y);
        *(__half2*)&sW[o * SH + kq * 4 + 2] = __floats2half2_rn(w.z, w.w);
    }
    for (int i = tid; i < 128; i += 512) sbo[i] = bout[i];
    for (int i = tid; i < TM * 32; i += 512)
        skl[i] = kw[((size_t)row0 * 32 + i) * st];
    __syncthreads();

    // ---- Gather phase: thread pair per (row, head), branch-free slots
    {
        const int p = tid & 1;            // 16-dim half selector
        const int h = (tid >> 1) & 3;     // head
        const int r = tid >> 3;           // row in tile
        const size_t e = (size_t)row0 + r;
        const int off = h * 32 + p * 16;  // offset into 128-wide head-major vec

        float q[16];
        {
            const uint4* qp = (const uint4*)&g_q[e * 128 + off];
            #pragma unroll
            for (int c = 0; c < 2; c++) {
                uint4 u = qp[c];
                const __half2* hp = (const __half2*)&u;
                #pragma unroll
                for (int pp = 0; pp < 4; pp++) {
                    float2 f = __half22float2(hp[pp]);
                    q[c*8 + pp*2] = f.x; q[c*8 + pp*2 + 1] = f.y;
                }
            }
        }

        const float scale = 0.17677669529663687f;   // 1/sqrt(32)
        float den = 0.f;
        float att[16];
        #pragma unroll
        for (int j = 0; j < 16; j++) att[j] = 0.f;

        #pragma unroll
        for (int s = 0; s < MAXK; s++) {
            int ii_raw = skl[r * 32 + s];
            bool valid = (ii_raw >= 0);
            int ii = valid ? min(ii_raw, EN - 1) : 0;
            int jj = skl[r * 32 + 16 + s];
            jj = min(max(jj, 0), EN - 1);

            const uint4* kp = (const uint4*)&g_kv[(size_t)ii * 256 + off];
            float d = 0.f;
            #pragma unroll
            for (int c = 0; c < 2; c++) {
                uint4 u = kp[c];
                const __half2* hp = (const __half2*)&u;
                #pragma unroll
                for (int pp = 0; pp < 4; pp++) {
                    float2 f = __half22float2(hp[pp]);
                    d += q[c*8 + pp*2] * f.x + q[c*8 + pp*2 + 1] * f.y;
                }
            }
            d += __shfl_xor_sync(0xFFFFFFFF, d, 1);   // pair reduction (converged)

            float w = valid ? __expf(scale * d + g_bh[(size_t)jj * NH + h]) : 0.f;
            den += valid ? w : 1.f;                   // exp(0) for masked slot

            const uint4* vp = (const uint4*)&g_kv[(size_t)ii * 256 + 128 + off];
            #pragma unroll
            for (int c = 0; c < 2; c++) {
                uint4 u = vp[c];
                const __half2* hp = (const __half2*)&u;
                #pragma unroll
                for (int pp = 0; pp < 4; pp++) {
                    float2 f = __half22float2(hp[pp]);
                    att[c*8 + pp*2]     += w * f.x;
                    att[c*8 + pp*2 + 1] += w * f.y;
                }
            }
        }

        // gate and write X (A operand for out GEMM)
        const float inv = 1.f / den;
        const uint4* gp = (const uint4*)&g_g[e * 128 + off];
        #pragma unroll
        for (int c = 0; c < 2; c++) {
            uint4 u = gp[c];
            const __half2* hp = (const __half2*)&u;
            #pragma unroll
            for (int pp = 0; pp < 4; pp++) {
                float2 gf = __half22float2(hp[pp]);
                *(__half2*)&sX[r * SH + off + c * 8 + pp * 2] =
                    __floats2half2_rn(gf.x * att[c*8 + pp*2] * inv,
                                      gf.y * att[c*8 + pp*2 + 1] * inv);
            }
        }
    }
    __syncthreads();

    // ---- Output GEMM: out = X @ Wout^T + bout. 16 warps: 4m x 4n.
    const int lane = tid & 31, wid = tid >> 5;
    const int g = lane >> 2, tig = lane & 3;
    const int rw = (wid & 3) * 16;      // row band
    const int cw = (wid >> 2) * 32;     // col band

    float acc[4][4] = {};
    #pragma unroll
    for (int k0 = 0; k0 < 8; k0++) {
        const __half* pa = sX + (rw + g) * SH + k0 * 16 + tig * 2;
        unsigned a0 = ldh2(pa);
        unsigned a1 = ldh2(pa + 8 * SH);
        unsigned a2 = ldh2(pa + 8);
        unsigned a3 = ldh2(pa + 8 * SH + 8);
        #pragma unroll
        for (int nt = 0; nt < 4; nt++) {
            const __half* pb = sW + (cw + nt * 8 + g) * SH + k0 * 16 + tig * 2;
            mma16816(acc[nt], a0, a1, a2, a3, ldh2(pb), ldh2(pb + 8));
        }
    }

    #pragma unroll
    for (int nt = 0; nt < 4; nt++) {
        int col = cw + nt * 8 + tig * 2;
        size_t e0 = (size_t)(row0 + rw + g);
        float2 o0 = make_float2(acc[nt][0] + sbo[col], acc[nt][1] + sbo[col + 1]);
        float2 o1 = make_float2(acc[nt][2] + sbo[col], acc[nt][3] + sbo[col + 1]);
        *(float2*)&out[e0 * 128 + col]       = o0;
        *(float2*)&out[(e0 + 8) * 128 + col] = o1;
    }
}

// ---------------------------------------------------------------------------
extern "C" void kernel_launch(void* const* d_in, const int* in_sizes, int n_in,
                              void* d_out, int out_size)
{
    // Locate Z and klist by element count; remaining inputs keep dict order:
    // Wq, Wk, Wv, Wb, Wg, bg, Wout, bout
    const float* Z = nullptr;
    const int*   klist = nullptr;
    const void*  rest[16];
    int nrest = 0;
    for (int i = 0; i < n_in; i++) {
        if (in_sizes[i] == 25600000)      Z     = (const float*)d_in[i];
        else if (in_sizes[i] == 6400000)  klist = (const int*)d_in[i];
        else                              rest[nrest++] = d_in[i];
    }
    const float* Wq   = (const float*)rest[0];
    const float* Wk   = (const float*)rest[1];
    const float* Wv   = (const float*)rest[2];
    const float* Wb   = (const float*)rest[3];
    const float* Wg   = (const float*)rest[4];
    const float* bg   = (const float*)rest[5];
    const float* Wout = (const float*)rest[6];
    const float* bout = (const float*)rest[7];
    float* out = (float*)d_out;

    const int smemP = (2 * PTM * SH + 256 * SH + 512) * 2 + 128 * 4;  // 105,984 B
    const int smemB = 192 * SH * 2 + 2048 * 4 + 128 * 4;              // 60,928 B

    cudaFuncSetAttribute(kproj2,   cudaFuncAttributeMaxDynamicSharedMemorySize, smemP);
    cudaFuncSetAttribute(katt_out, cudaFuncAttributeMaxDynamicSharedMemorySize, smemB);

    kproj2  <<<2 * PHALF, 512, smemP>>>(Z, Wk, Wv, Wq, Wg, Wb, bg, klist);
    katt_out<<<NBLK, 512, smemB>>>(klist, Wout, bout, out);
}

// round 15
// speedup vs baseline: 1.0455x; 1.0455x over previous
#include <cuda_runtime.h>
#include <cuda_fp16.h>
#include <math.h>
#include <stdint.h>

// Problem constants
#define EN      200000
#define IND     128
#define HIDD    32
#define NH      4
#define OUTD    128
#define MAXK    16
#define TM      64                     // rows per block (attention kernel)
#define NBLK    (EN / TM)              // 3125
#define PTM     128                    // rows per tile (projection kernel)
#define PTILES  ((EN + PTM - 1) / PTM) // 1563
#define PGRID   148
#define SH      136                    // smem row stride in halfs (128 + 8 pad)

// Scratch (device globals; no allocation)
__device__ __half g_kv[(size_t)EN * 256];  // [e][0:128]=k (head-major), [128:256]=v
__device__ __half g_q [(size_t)EN * 128];  // q, head-major
__device__ __half g_g [(size_t)EN * 128];  // sigmoid gate, head-major
__device__ float  g_bh[(size_t)EN * NH];   // [e][h]
__device__ int    g_kstride;               // 2 if klist is int64, 1 if int32

// m16n8k16 f16 MMA, fp32 accum. A row-major frag, B col-major frag.
__device__ __forceinline__ void mma16816(float c[4], unsigned a0, unsigned a1,
                                         unsigned a2, unsigned a3,
                                         unsigned b0, unsigned b1)
{
    asm volatile(
        "mma.sync.aligned.m16n8k16.row.col.f32.f16.f16.f32 "
        "{%0,%1,%2,%3}, {%4,%5,%6,%7}, {%8,%9}, {%0,%1,%2,%3};\n"
        : "+f"(c[0]), "+f"(c[1]), "+f"(c[2]), "+f"(c[3])
        : "r"(a0), "r"(a1), "r"(a2), "r"(a3), "r"(b0), "r"(b1));
}

__device__ __forceinline__ unsigned ldh2(const __half* p) { return *(const unsigned*)p; }

// ---------------------------------------------------------------------------
// Kernel A: ALL projections. 148 persistent blocks, 512 threads, double-
// buffered 128-row Z tiles. All four weight matrices resident in smem.
// chunk0=K, chunk1=V (-> g_kv), chunk2=Q (-> g_q), chunk3=G (sigmoid -> g_g).
// Plus per-row b = Z@Wb (-> g_bh) and klist width detection (block 0).
// ---------------------------------------------------------------------------
__global__ void __launch_bounds__(512, 1) kproj_all(
    const float* __restrict__ Z,
    const float* __restrict__ Wk,
    const float* __restrict__ Wv,
    const float* __restrict__ Wq,
    const float* __restrict__ Wg,
    const float* __restrict__ Wb,
    const float* __restrict__ bgv,
    const int*   __restrict__ kw)
{
    extern __shared__ __half sh[];
    __half* sZ0 = sh;                             // [128][SH]
    __half* sZ1 = sh + PTM * SH;                  // [128][SH]
    __half* sW  = sh + 2 * PTM * SH;              // [4][128][SH]
    __half* sWb = sh + 2 * PTM * SH + 4 * 128 * SH;  // [512]
    float*  sbg = (float*)(sWb + 512);            // [128]

    const int tid = threadIdx.x;

    if (blockIdx.x == 0 && tid == 0) {
        int is64 = 1;
        for (int i = 0; i < 4096; i++) {
            int hi = kw[2 * i + 1];
            if (hi != 0 && hi != -1) { is64 = 0; break; }
        }
        g_kstride = is64 ? 2 : 1;
    }

    // Stage all weights once
    const float* Wsrcs[4] = {Wk, Wv, Wq, Wg};
    #pragma unroll
    for (int c = 0; c < 4; c++) {
        const float* Wsrc = Wsrcs[c];
        __half* dst = sW + c * 128 * SH;
        for (int i = tid; i < 128 * 32; i += 512) {
            int col = i >> 5, kq = i & 31;
            float4 w = *(const float4*)(Wsrc + (size_t)col * IND + kq * 4);
            *(__half2*)&dst[col * SH + kq * 4]     = __floats2half2_rn(w.x, w.y);
            *(__half2*)&dst[col * SH + kq * 4 + 2] = __floats2half2_rn(w.z, w.w);
        }
    }
    for (int i = tid; i < NH * IND; i += 512) sWb[i] = __float2half_rn(Wb[i]);
    for (int i = tid; i < 128; i += 512) sbg[i] = bgv[i];

    const int lane = tid & 31, wid = tid >> 5;
    const int g = lane >> 2, tig = lane & 3;
    const int rb = (wid & 7) * 16;    // row band 0..112
    const int cb = (wid >> 3) * 64;   // col band 0,64

    // Tile loader (fp32 -> fp16), 128 rows
    auto load_tile = [&](int t, __half* dstZ) {
        const int row0 = t * PTM;
        for (int i = tid; i < PTM * 32; i += 512) {
            int r = i >> 5, c = i & 31;
            int rg = row0 + r; if (rg >= EN) rg = EN - 1;
            float4 v = *(const float4*)(Z + (size_t)rg * IND + c * 4);
            *(__half2*)&dstZ[r * SH + c * 4]     = __floats2half2_rn(v.x, v.y);
            *(__half2*)&dstZ[r * SH + c * 4 + 2] = __floats2half2_rn(v.z, v.w);
        }
    };

    int t = blockIdx.x;
    if (t < PTILES) load_tile(t, sZ0);
    __syncthreads();

    int buf = 0;
    for (; t < PTILES; t += PGRID) {
        __half* sZ = buf ? sZ1 : sZ0;
        __half* sZn = buf ? sZ0 : sZ1;

        // Prefetch next tile into the other buffer (overlaps with MMA below)
        int tn = t + PGRID;
        if (tn < PTILES) load_tile(tn, sZn);

        const int row0 = t * PTM;
        const int r0g = row0 + rb + g;

        #pragma unroll
        for (int chunk = 0; chunk < 4; chunk++) {
            const __half* Wc = sW + chunk * 128 * SH;
            float acc[8][4] = {};
            #pragma unroll
            for (int k0 = 0; k0 < 8; k0++) {
                const __half* pa = sZ + (rb + g) * SH + k0 * 16 + tig * 2;
                unsigned a0 = ldh2(pa);
                unsigned a1 = ldh2(pa + 8 * SH);
                unsigned a2 = ldh2(pa + 8);
                unsigned a3 = ldh2(pa + 8 * SH + 8);
                #pragma unroll
                for (int nt = 0; nt < 8; nt++) {
                    const __half* pb = Wc + (cb + nt * 8 + g) * SH + k0 * 16 + tig * 2;
                    mma16816(acc[nt], a0, a1, a2, a3, ldh2(pb), ldh2(pb + 8));
                }
            }

            if (chunk < 2) {
                #pragma unroll
                for (int nt = 0; nt < 8; nt++) {
                    int col = chunk * 128 + cb + nt * 8 + tig * 2;
                    if (r0g < EN)
                        *(__half2*)&g_kv[(size_t)r0g * 256 + col] =
                            __floats2half2_rn(acc[nt][0], acc[nt][1]);
                    if (r0g + 8 < EN)
                        *(__half2*)&g_kv[(size_t)(r0g + 8) * 256 + col] =
                            __floats2half2_rn(acc[nt][2], acc[nt][3]);
                }
            } else if (chunk == 2) {
                #pragma unroll
                for (int nt = 0; nt < 8; nt++) {
                    int col = cb + nt * 8 + tig * 2;
                    if (r0g < EN)
                        *(__half2*)&g_q[(size_t)r0g * 128 + col] =
                            __floats2half2_rn(acc[nt][0], acc[nt][1]);
                    if (r0g + 8 < EN)
                        *(__half2*)&g_q[(size_t)(r0g + 8) * 128 + col] =
                            __floats2half2_rn(acc[nt][2], acc[nt][3]);
                }
            } else {
                #pragma unroll
                for (int nt = 0; nt < 8; nt++) {
                    int col = cb + nt * 8 + tig * 2;
                    float g0 = 1.f / (1.f + __expf(-(acc[nt][0] + sbg[col])));
                    float g1 = 1.f / (1.f + __expf(-(acc[nt][1] + sbg[col + 1])));
                    float g2 = 1.f / (1.f + __expf(-(acc[nt][2] + sbg[col])));
                    float g3 = 1.f / (1.f + __expf(-(acc[nt][3] + sbg[col + 1])));
                    if (r0g < EN)
                        *(__half2*)&g_g[(size_t)r0g * 128 + col] = __floats2half2_rn(g0, g1);
                    if (r0g + 8 < EN)
                        *(__half2*)&g_g[(size_t)(r0g + 8) * 128 + col] = __floats2half2_rn(g2, g3);
                }
            }
        }

        // b tail: 512 (row, head) dots, one per thread
        {
            int r = tid >> 2, h = tid & 3;
            int rg = row0 + r;
            if (rg < EN) {
                float s = 0.f;
                #pragma unroll 8
                for (int k = 0; k < 128; k += 2) {
                    float2 a = __half22float2(*(__half2*)&sZ[r * SH + k]);
                    float2 b = __half22float2(*(__half2*)&sWb[h * IND + k]);
                    s += a.x * b.x + a.y * b.y;
                }
                g_bh[(size_t)rg * NH + h] = s;
            }
        }

        __syncthreads();   // next-tile stores complete; current tile consumed
        buf ^= 1;
    }
}

// ---------------------------------------------------------------------------
// Kernel B: gather attention + gating + output GEMM. 512 threads, 64 rows.
// A thread PAIR handles one (row, head): p = tid&1 selects 16-dim half.
// K-dot accumulates in HALF2 (HFMA2) with q resident as half2; V accumulation
// stays fp32. Branch-free slot loop keeps the pair shuffle converged.
// ---------------------------------------------------------------------------
__global__ void __launch_bounds__(512, 2) katt_out(
    const int*   __restrict__ kw,
    const float* __restrict__ Wout,
    const float* __restrict__ bout,
    float*       __restrict__ out)
{
    extern __shared__ __half sh[];
    __half* sX  = sh;                          // [64][SH]  gated X (A operand)
    __half* sW  = sh + 64 * SH;                // [128][SH] Wout (B operand)
    int*    skl = (int*)(sh + 192 * SH);       // [64][32]
    float*  sbo = (float*)(skl + 2048);        // [128]

    const int tid  = threadIdx.x;
    const int row0 = blockIdx.x * TM;
    const int st   = g_kstride;

    // Stage Wout + bout + klist
    const float4* W4 = (const float4*)Wout;
    for (int i = tid; i < 128 * 32; i += 512) {
        int o = i >> 5, kq = i & 31;
        float4 w = W4[o * 32 + kq];
        *(__half2*)&sW[o * SH + kq * 4]     = __floats2half2_rn(w.x, w.y);
        *(__half2*)&sW[o * SH + kq * 4 + 2] = __floats2half2_rn(w.z, w.w);
    }
    for (int i = tid; i < 128; i += 512) sbo[i] = bout[i];
    for (int i = tid; i < TM * 32; i += 512)
        skl[i] = kw[((size_t)row0 * 32 + i) * st];
    __syncthreads();

    // ---- Gather phase: thread pair per (row, head), branch-free slots
    {
        const int p = tid & 1;            // 16-dim half selector
        const int h = (tid >> 1) & 3;     // head
        const int r = tid >> 3;           // row in tile
        const size_t e = (size_t)row0 + r;
        const int off = h * 32 + p * 16;  // offset into 128-wide head-major vec

        // q resident as half2 (no conversion)
        __half2 q2[8];
        {
            const uint4* qp = (const uint4*)&g_q[e * 128 + off];
            uint4 u0 = qp[0], u1 = qp[1];
            const __half2* h0 = (const __half2*)&u0;
            const __half2* h1 = (const __half2*)&u1;
            #pragma unroll
            for (int pp = 0; pp < 4; pp++) { q2[pp] = h0[pp]; q2[4 + pp] = h1[pp]; }
        }

        const float scale = 0.17677669529663687f;   // 1/sqrt(32)
        float den = 0.f;
        float att[16];
        #pragma unroll
        for (int j = 0; j < 16; j++) att[j] = 0.f;

        #pragma unroll
        for (int s = 0; s < MAXK; s++) {
            int ii_raw = skl[r * 32 + s];
            bool valid = (ii_raw >= 0);
            int ii = valid ? min(ii_raw, EN - 1) : 0;
            int jj = skl[r * 32 + 16 + s];
            jj = min(max(jj, 0), EN - 1);

            const uint4* kp = (const uint4*)&g_kv[(size_t)ii * 256 + off];
            uint4 uk0 = kp[0], uk1 = kp[1];
            __half2 d2 = __floats2half2_rn(0.f, 0.f);
            {
                const __half2* h0 = (const __half2*)&uk0;
                const __half2* h1 = (const __half2*)&uk1;
                #pragma unroll
                for (int pp = 0; pp < 4; pp++) d2 = __hfma2(q2[pp], h0[pp], d2);
                #pragma unroll
                for (int pp = 0; pp < 4; pp++) d2 = __hfma2(q2[4 + pp], h1[pp], d2);
            }
            float2 df = __half22float2(d2);
            float d = df.x + df.y;
            d += __shfl_xor_sync(0xFFFFFFFF, d, 1);   // pair reduction (converged)

            float w = valid ? __expf(scale * d + g_bh[(size_t)jj * NH + h]) : 0.f;
            den += valid ? w : 1.f;                   // exp(0) for masked slot

            const uint4* vp = (const uint4*)&g_kv[(size_t)ii * 256 + 128 + off];
            uint4 uv0 = vp[0], uv1 = vp[1];
            {
                const __half2* h0 = (const __half2*)&uv0;
                const __half2* h1 = (const __half2*)&uv1;
                #pragma unroll
                for (int pp = 0; pp < 4; pp++) {
                    float2 f0 = __half22float2(h0[pp]);
                    float2 f1 = __half22float2(h1[pp]);
                    att[pp*2]       += w * f0.x;
                    att[pp*2 + 1]   += w * f0.y;
                    att[8 + pp*2]   += w * f1.x;
                    att[8 + pp*2+1] += w * f1.y;
                }
            }
        }

        // gate and write X (A operand for out GEMM)
        const float inv = 1.f / den;
        const uint4* gp = (const uint4*)&g_g[e * 128 + off];
        uint4 ug0 = gp[0], ug1 = gp[1];
        const __half2* hg0 = (const __half2*)&ug0;
        const __half2* hg1 = (const __half2*)&ug1;
        #pragma unroll
        for (int pp = 0; pp < 4; pp++) {
            float2 f0 = __half22float2(hg0[pp]);
            float2 f1 = __half22float2(hg1[pp]);
            *(__half2*)&sX[r * SH + off + pp * 2] =
                __floats2half2_rn(f0.x * att[pp*2] * inv, f0.y * att[pp*2+1] * inv);
            *(__half2*)&sX[r * SH + off + 8 + pp * 2] =
                __floats2half2_rn(f1.x * att[8 + pp*2] * inv, f1.y * att[8 + pp*2+1] * inv);
        }
    }
    __syncthreads();

    // ---- Output GEMM: out = X @ Wout^T + bout. 16 warps: 4m x 4n.
    const int lane = tid & 31, wid = tid >> 5;
    const int g = lane >> 2, tig = lane & 3;
    const int rw = (wid & 3) * 16;      // row band
    const int cw = (wid >> 2) * 32;     // col band

    float acc[4][4] = {};
    #pragma unroll
    for (int k0 = 0; k0 < 8; k0++) {
        const __half* pa = sX + (rw + g) * SH + k0 * 16 + tig * 2;
        unsigned a0 = ldh2(pa);
        unsigned a1 = ldh2(pa + 8 * SH);
        unsigned a2 = ldh2(pa + 8);
        unsigned a3 = ldh2(pa + 8 * SH + 8);
        #pragma unroll
        for (int nt = 0; nt < 4; nt++) {
            const __half* pb = sW + (cw + nt * 8 + g) * SH + k0 * 16 + tig * 2;
            mma16816(acc[nt], a0, a1, a2, a3, ldh2(pb), ldh2(pb + 8));
        }
    }

    #pragma unroll
    for (int nt = 0; nt < 4; nt++) {
        int col = cw + nt * 8 + tig * 2;
        size_t e0 = (size_t)(row0 + rw + g);
        float2 o0 = make_float2(acc[nt][0] + sbo[col], acc[nt][1] + sbo[col + 1]);
        float2 o1 = make_float2(acc[nt][2] + sbo[col], acc[nt][3] + sbo[col + 1]);
        *(float2*)&out[e0 * 128 + col]       = o0;
        *(float2*)&out[(e0 + 8) * 128 + col] = o1;
    }
}

// ---------------------------------------------------------------------------
extern "C" void kernel_launch(void* const* d_in, const int* in_sizes, int n_in,
                              void* d_out, int out_size)
{
    // Locate Z and klist by element count; remaining inputs keep dict order:
    // Wq, Wk, Wv, Wb, Wg, bg, Wout, bout
    const float* Z = nullptr;
    const int*   klist = nullptr;
    const void*  rest[16];
    int nrest = 0;
    for (int i = 0; i < n_in; i++) {
        if (in_sizes[i] == 25600000)      Z     = (const float*)d_in[i];
        else if (in_sizes[i] == 6400000)  klist = (const int*)d_in[i];
        else                              rest[nrest++] = d_in[i];
    }
    const float* Wq   = (const float*)rest[0];
    const float* Wk   = (const float*)rest[1];
    const float* Wv   = (const float*)rest[2];
    const float* Wb   = (const float*)rest[3];
    const float* Wg   = (const float*)rest[4];
    const float* bg   = (const float*)rest[5];
    const float* Wout = (const float*)rest[6];
    const float* bout = (const float*)rest[7];
    float* out = (float*)d_out;

    const int smemP = (2 * PTM * SH + 4 * 128 * SH + 512) * 2 + 128 * 4;  // 210,432 B
    const int smemB = 192 * SH * 2 + 2048 * 4 + 128 * 4;                  // 60,928 B

    cudaFuncSetAttribute(kproj_all, cudaFuncAttributeMaxDynamicSharedMemorySize, smemP);
    cudaFuncSetAttribute(katt_out,  cudaFuncAttributeMaxDynamicSharedMemorySize, smemB);

    kproj_all<<<PGRID, 512, smemP>>>(Z, Wk, Wv, Wq, Wg, Wb, bg, klist);
    katt_out <<<NBLK, 512, smemB>>>(klist, Wout, bout, out);
}

// round 16
// speedup vs baseline: 1.1073x; 1.0591x over previous
#include <cuda_runtime.h>
#include <cuda_fp16.h>
#include <math.h>
#include <stdint.h>

// Problem constants
#define EN      200000
#define IND     128
#define HIDD    32
#define NH      4
#define OUTD    128
#define MAXK    16
#define TM      64                     // rows per block (attention kernel)
#define NBLK    (EN / TM)              // 3125
#define PTM     128                    // rows per tile (projection kernel)
#define PTILES  ((EN + PTM - 1) / PTM) // 1563
#define PGRID   148
#define SH      136                    // smem row stride in halfs (128 + 8 pad)

// Scratch (device globals; no allocation)
__device__ __half g_kv[(size_t)EN * 256];  // [e][0:128]=k (head-major), [128:256]=v
__device__ __half g_q [(size_t)EN * 128];  // q, head-major
__device__ __half g_g [(size_t)EN * 128];  // sigmoid gate, head-major
__device__ float  g_bh[(size_t)EN * NH];   // [e][h]
__device__ int    g_kstride;               // 2 if klist is int64, 1 if int32

// m16n8k16 f16 MMA, fp32 accum. A row-major frag, B col-major frag.
__device__ __forceinline__ void mma16816(float c[4], unsigned a0, unsigned a1,
                                         unsigned a2, unsigned a3,
                                         unsigned b0, unsigned b1)
{
    asm volatile(
        "mma.sync.aligned.m16n8k16.row.col.f32.f16.f16.f32 "
        "{%0,%1,%2,%3}, {%4,%5,%6,%7}, {%8,%9}, {%0,%1,%2,%3};\n"
        : "+f"(c[0]), "+f"(c[1]), "+f"(c[2]), "+f"(c[3])
        : "r"(a0), "r"(a1), "r"(a2), "r"(a3), "r"(b0), "r"(b1));
}

__device__ __forceinline__ unsigned ldh2(const __half* p) { return *(const unsigned*)p; }

// ---------------------------------------------------------------------------
// Kernel A: ALL projections. 148 persistent blocks, 512 threads, double-
// buffered 128-row Z tiles. All four weight matrices resident in smem.
// chunk0=K, chunk1=V (-> g_kv), chunk2=Q (-> g_q), chunk3=G (sigmoid -> g_g).
// Plus per-row b = Z@Wb (-> g_bh) and klist width detection (block 0).
// ---------------------------------------------------------------------------
__global__ void __launch_bounds__(512, 1) kproj_all(
    const float* __restrict__ Z,
    const float* __restrict__ Wk,
    const float* __restrict__ Wv,
    const float* __restrict__ Wq,
    const float* __restrict__ Wg,
    const float* __restrict__ Wb,
    const float* __restrict__ bgv,
    const int*   __restrict__ kw)
{
    extern __shared__ __half sh[];
    __half* sZ0 = sh;                             // [128][SH]
    __half* sZ1 = sh + PTM * SH;                  // [128][SH]
    __half* sW  = sh + 2 * PTM * SH;              // [4][128][SH]
    __half* sWb = sh + 2 * PTM * SH + 4 * 128 * SH;  // [512]
    float*  sbg = (float*)(sWb + 512);            // [128]

    const int tid = threadIdx.x;

    if (blockIdx.x == 0 && tid == 0) {
        int is64 = 1;
        for (int i = 0; i < 4096; i++) {
            int hi = kw[2 * i + 1];
            if (hi != 0 && hi != -1) { is64 = 0; break; }
        }
        g_kstride = is64 ? 2 : 1;
    }

    // Stage all weights once
    const float* Wsrcs[4] = {Wk, Wv, Wq, Wg};
    #pragma unroll
    for (int c = 0; c < 4; c++) {
        const float* Wsrc = Wsrcs[c];
        __half* dst = sW + c * 128 * SH;
        for (int i = tid; i < 128 * 32; i += 512) {
            int col = i >> 5, kq = i & 31;
            float4 w = *(const float4*)(Wsrc + (size_t)col * IND + kq * 4);
            *(__half2*)&dst[col * SH + kq * 4]     = __floats2half2_rn(w.x, w.y);
            *(__half2*)&dst[col * SH + kq * 4 + 2] = __floats2half2_rn(w.z, w.w);
        }
    }
    for (int i = tid; i < NH * IND; i += 512) sWb[i] = __float2half_rn(Wb[i]);
    for (int i = tid; i < 128; i += 512) sbg[i] = bgv[i];

    const int lane = tid & 31, wid = tid >> 5;
    const int g = lane >> 2, tig = lane & 3;
    const int rb = (wid & 7) * 16;    // row band 0..112
    const int cb = (wid >> 3) * 64;   // col band 0,64

    // Tile loader (fp32 -> fp16), 128 rows
    auto load_tile = [&](int t, __half* dstZ) {
        const int row0 = t * PTM;
        for (int i = tid; i < PTM * 32; i += 512) {
            int r = i >> 5, c = i & 31;
            int rg = row0 + r; if (rg >= EN) rg = EN - 1;
            float4 v = *(const float4*)(Z + (size_t)rg * IND + c * 4);
            *(__half2*)&dstZ[r * SH + c * 4]     = __floats2half2_rn(v.x, v.y);
            *(__half2*)&dstZ[r * SH + c * 4 + 2] = __floats2half2_rn(v.z, v.w);
        }
    };

    int t = blockIdx.x;
    if (t < PTILES) load_tile(t, sZ0);
    __syncthreads();

    int buf = 0;
    for (; t < PTILES; t += PGRID) {
        __half* sZ = buf ? sZ1 : sZ0;
        __half* sZn = buf ? sZ0 : sZ1;

        // Prefetch next tile into the other buffer (overlaps with MMA below)
        int tn = t + PGRID;
        if (tn < PTILES) load_tile(tn, sZn);

        const int row0 = t * PTM;
        const int r0g = row0 + rb + g;

        #pragma unroll
        for (int chunk = 0; chunk < 4; chunk++) {
            const __half* Wc = sW + chunk * 128 * SH;
            float acc[8][4] = {};
            #pragma unroll
            for (int k0 = 0; k0 < 8; k0++) {
                const __half* pa = sZ + (rb + g) * SH + k0 * 16 + tig * 2;
                unsigned a0 = ldh2(pa);
                unsigned a1 = ldh2(pa + 8 * SH);
                unsigned a2 = ldh2(pa + 8);
                unsigned a3 = ldh2(pa + 8 * SH + 8);
                #pragma unroll
                for (int nt = 0; nt < 8; nt++) {
                    const __half* pb = Wc + (cb + nt * 8 + g) * SH + k0 * 16 + tig * 2;
                    mma16816(acc[nt], a0, a1, a2, a3, ldh2(pb), ldh2(pb + 8));
                }
            }

            if (chunk < 2) {
                #pragma unroll
                for (int nt = 0; nt < 8; nt++) {
                    int col = chunk * 128 + cb + nt * 8 + tig * 2;
                    if (r0g < EN)
                        *(__half2*)&g_kv[(size_t)r0g * 256 + col] =
                            __floats2half2_rn(acc[nt][0], acc[nt][1]);
                    if (r0g + 8 < EN)
                        *(__half2*)&g_kv[(size_t)(r0g + 8) * 256 + col] =
                            __floats2half2_rn(acc[nt][2], acc[nt][3]);
                }
            } else if (chunk == 2) {
                #pragma unroll
                for (int nt = 0; nt < 8; nt++) {
                    int col = cb + nt * 8 + tig * 2;
                    if (r0g < EN)
                        *(__half2*)&g_q[(size_t)r0g * 128 + col] =
                            __floats2half2_rn(acc[nt][0], acc[nt][1]);
                    if (r0g + 8 < EN)
                        *(__half2*)&g_q[(size_t)(r0g + 8) * 128 + col] =
                            __floats2half2_rn(acc[nt][2], acc[nt][3]);
                }
            } else {
                #pragma unroll
                for (int nt = 0; nt < 8; nt++) {
                    int col = cb + nt * 8 + tig * 2;
                    float g0 = 1.f / (1.f + __expf(-(acc[nt][0] + sbg[col])));
                    float g1 = 1.f / (1.f + __expf(-(acc[nt][1] + sbg[col + 1])));
                    float g2 = 1.f / (1.f + __expf(-(acc[nt][2] + sbg[col])));
                    float g3 = 1.f / (1.f + __expf(-(acc[nt][3] + sbg[col + 1])));
                    if (r0g < EN)
                        *(__half2*)&g_g[(size_t)r0g * 128 + col] = __floats2half2_rn(g0, g1);
                    if (r0g + 8 < EN)
                        *(__half2*)&g_g[(size_t)(r0g + 8) * 128 + col] = __floats2half2_rn(g2, g3);
                }
            }
        }

        // b tail: 512 (row, head) dots, one per thread
        {
            int r = tid >> 2, h = tid & 3;
            int rg = row0 + r;
            if (rg < EN) {
                float s = 0.f;
                #pragma unroll 8
                for (int k = 0; k < 128; k += 2) {
                    float2 a = __half22float2(*(__half2*)&sZ[r * SH + k]);
                    float2 b = __half22float2(*(__half2*)&sWb[h * IND + k]);
                    s += a.x * b.x + a.y * b.y;
                }
                g_bh[(size_t)rg * NH + h] = s;
            }
        }

        __syncthreads();   // next-tile stores complete; current tile consumed
        buf ^= 1;
    }
}

// ---------------------------------------------------------------------------
// Kernel B: gather attention + gating + output GEMM. 512 threads, 64 rows.
// Thread PAIR per (row, head); K-dot and V-accumulation both in HFMA2, with
// V partials flushed to fp32 every 4 slots. klist read as int4 per group.
// Branch-free slot loop keeps the pair shuffle converged.
// ---------------------------------------------------------------------------
__global__ void __launch_bounds__(512, 2) katt_out(
    const int*   __restrict__ kw,
    const float* __restrict__ Wout,
    const float* __restrict__ bout,
    float*       __restrict__ out)
{
    extern __shared__ __half sh[];
    __half* sX  = sh;                          // [64][SH]  gated X (A operand)
    __half* sW  = sh + 64 * SH;                // [128][SH] Wout (B operand)
    int*    skl = (int*)(sh + 192 * SH);       // [64][32]
    float*  sbo = (float*)(skl + 2048);        // [128]

    const int tid  = threadIdx.x;
    const int row0 = blockIdx.x * TM;
    const int st   = g_kstride;

    // Stage Wout + bout + klist
    const float4* W4 = (const float4*)Wout;
    for (int i = tid; i < 128 * 32; i += 512) {
        int o = i >> 5, kq = i & 31;
        float4 w = W4[o * 32 + kq];
        *(__half2*)&sW[o * SH + kq * 4]     = __floats2half2_rn(w.x, w.y);
        *(__half2*)&sW[o * SH + kq * 4 + 2] = __floats2half2_rn(w.z, w.w);
    }
    for (int i = tid; i < 128; i += 512) sbo[i] = bout[i];
    for (int i = tid; i < TM * 32; i += 512)
        skl[i] = kw[((size_t)row0 * 32 + i) * st];
    __syncthreads();

    // ---- Gather phase: thread pair per (row, head), branch-free slots
    {
        const int p = tid & 1;            // 16-dim half selector
        const int h = (tid >> 1) & 3;     // head
        const int r = tid >> 3;           // row in tile
        const size_t e = (size_t)row0 + r;
        const int off = h * 32 + p * 16;  // offset into 128-wide head-major vec

        // q resident as half2 (no conversion)
        __half2 q2[8];
        {
            const uint4* qp = (const uint4*)&g_q[e * 128 + off];
            uint4 u0 = qp[0], u1 = qp[1];
            const __half2* h0 = (const __half2*)&u0;
            const __half2* h1 = (const __half2*)&u1;
            #pragma unroll
            for (int pp = 0; pp < 4; pp++) { q2[pp] = h0[pp]; q2[4 + pp] = h1[pp]; }
        }

        const float scale = 0.17677669529663687f;   // 1/sqrt(32)
        float den = 0.f;
        float att[16];
        #pragma unroll
        for (int j = 0; j < 16; j++) att[j] = 0.f;

        #pragma unroll
        for (int sb = 0; sb < 4; sb++) {            // 4 groups of 4 slots
            int4 ii4 = *(const int4*)&skl[r * 32 + sb * 4];
            int4 jj4 = *(const int4*)&skl[r * 32 + 16 + sb * 4];
            int iis[4] = {ii4.x, ii4.y, ii4.z, ii4.w};
            int jjs[4] = {jj4.x, jj4.y, jj4.z, jj4.w};

            __half2 att2[8];                        // fp16 partial for this group
            #pragma unroll
            for (int pp = 0; pp < 8; pp++) att2[pp] = __floats2half2_rn(0.f, 0.f);

            #pragma unroll
            for (int s4 = 0; s4 < 4; s4++) {
                int ii_raw = iis[s4];
                bool valid = (ii_raw >= 0);
                int ii = valid ? min(ii_raw, EN - 1) : 0;
                int jj = min(max(jjs[s4], 0), EN - 1);

                const uint4* kp = (const uint4*)&g_kv[(size_t)ii * 256 + off];
                uint4 uk0 = kp[0], uk1 = kp[1];
                __half2 d2 = __floats2half2_rn(0.f, 0.f);
                {
                    const __half2* h0 = (const __half2*)&uk0;
                    const __half2* h1 = (const __half2*)&uk1;
                    #pragma unroll
                    for (int pp = 0; pp < 4; pp++) d2 = __hfma2(q2[pp], h0[pp], d2);
                    #pragma unroll
                    for (int pp = 0; pp < 4; pp++) d2 = __hfma2(q2[4 + pp], h1[pp], d2);
                }
                float2 df = __half22float2(d2);
                float d = df.x + df.y;
                d += __shfl_xor_sync(0xFFFFFFFF, d, 1);   // pair reduction

                float w = valid ? __expf(scale * d + g_bh[(size_t)jj * NH + h]) : 0.f;
                den += valid ? w : 1.f;                   // exp(0) for masked slot
                __half2 w2 = __float2half2_rn(w);

                const uint4* vp = (const uint4*)&g_kv[(size_t)ii * 256 + 128 + off];
                uint4 uv0 = vp[0], uv1 = vp[1];
                {
                    const __half2* v0 = (const __half2*)&uv0;
                    const __half2* v1 = (const __half2*)&uv1;
                    #pragma unroll
                    for (int pp = 0; pp < 4; pp++) att2[pp]     = __hfma2(w2, v0[pp], att2[pp]);
                    #pragma unroll
                    for (int pp = 0; pp < 4; pp++) att2[4 + pp] = __hfma2(w2, v1[pp], att2[4 + pp]);
                }
            }

            // flush fp16 partials to fp32
            #pragma unroll
            for (int pp = 0; pp < 8; pp++) {
                float2 f = __half22float2(att2[pp]);
                att[pp * 2]     += f.x;
                att[pp * 2 + 1] += f.y;
            }
        }

        // gate and write X (A operand for out GEMM)
        const float inv = 1.f / den;
        const uint4* gp = (const uint4*)&g_g[e * 128 + off];
        uint4 ug0 = gp[0], ug1 = gp[1];
        const __half2* hg0 = (const __half2*)&ug0;
        const __half2* hg1 = (const __half2*)&ug1;
        #pragma unroll
        for (int pp = 0; pp < 4; pp++) {
            float2 f0 = __half22float2(hg0[pp]);
            float2 f1 = __half22float2(hg1[pp]);
            *(__half2*)&sX[r * SH + off + pp * 2] =
                __floats2half2_rn(f0.x * att[pp*2] * inv, f0.y * att[pp*2+1] * inv);
            *(__half2*)&sX[r * SH + off + 8 + pp * 2] =
                __floats2half2_rn(f1.x * att[8 + pp*2] * inv, f1.y * att[8 + pp*2+1] * inv);
        }
    }
    __syncthreads();

    // ---- Output GEMM: out = X @ Wout^T + bout. 16 warps: 4m x 4n.
    const int lane = tid & 31, wid = tid >> 5;
    const int g = lane >> 2, tig = lane & 3;
    const int rw = (wid & 3) * 16;      // row band
    const int cw = (wid >> 2) * 32;     // col band

    float acc[4][4] = {};
    #pragma unroll
    for (int k0 = 0; k0 < 8; k0++) {
        const __half* pa = sX + (rw + g) * SH + k0 * 16 + tig * 2;
        unsigned a0 = ldh2(pa);
        unsigned a1 = ldh2(pa + 8 * SH);
        unsigned a2 = ldh2(pa + 8);
        unsigned a3 = ldh2(pa + 8 * SH + 8);
        #pragma unroll
        for (int nt = 0; nt < 4; nt++) {
            const __half* pb = sW + (cw + nt * 8 + g) * SH + k0 * 16 + tig * 2;
            mma16816(acc[nt], a0, a1, a2, a3, ldh2(pb), ldh2(pb + 8));
        }
    }

    #pragma unroll
    for (int nt = 0; nt < 4; nt++) {
        int col = cw + nt * 8 + tig * 2;
        size_t e0 = (size_t)(row0 + rw + g);
        float2 o0 = make_float2(acc[nt][0] + sbo[col], acc[nt][1] + sbo[col + 1]);
        float2 o1 = make_float2(acc[nt][2] + sbo[col], acc[nt][3] + sbo[col + 1]);
        *(float2*)&out[e0 * 128 + col]       = o0;
        *(float2*)&out[(e0 + 8) * 128 + col] = o1;
    }
}

// ---------------------------------------------------------------------------
extern "C" void kernel_launch(void* const* d_in, const int* in_sizes, int n_in,
                              void* d_out, int out_size)
{
    // Locate Z and klist by element count; remaining inputs keep dict order:
    // Wq, Wk, Wv, Wb, Wg, bg, Wout, bout
    const float* Z = nullptr;
    const int*   klist = nullptr;
    const void*  rest[16];
    int nrest = 0;
    for (int i = 0; i < n_in; i++) {
        if (in_sizes[i] == 25600000)      Z     = (const float*)d_in[i];
        else if (in_sizes[i] == 6400000)  klist = (const int*)d_in[i];
        else                              rest[nrest++] = d_in[i];
    }
    const float* Wq   = (const float*)rest[0];
    const float* Wk   = (const float*)rest[1];
    const float* Wv   = (const float*)rest[2];
    const float* Wb   = (const float*)rest[3];
    const float* Wg   = (const float*)rest[4];
    const float* bg   = (const float*)rest[5];
    const float* Wout = (const float*)rest[6];
    const float* bout = (const float*)rest[7];
    float* out = (float*)d_out;

    const int smemP = (2 * PTM * SH + 4 * 128 * SH + 512) * 2 + 128 * 4;  // 210,432 B
    const int smemB = 192 * SH * 2 + 2048 * 4 + 128 * 4;                  // 60,928 B

    cudaFuncSetAttribute(kproj_all, cudaFuncAttributeMaxDynamicSharedMemorySize, smemP);
    cudaFuncSetAttribute(katt_out,  cudaFuncAttributeMaxDynamicSharedMemorySize, smemB);

    kproj_all<<<PGRID, 512, smemP>>>(Z, Wk, Wv, Wq, Wg, Wb, bg, klist);
    katt_out <<<NBLK, 512, smemB>>>(klist, Wout, bout, out);
}

// round 17
// speedup vs baseline: 1.1630x; 1.0503x over previous
#include <cuda_runtime.h>
#include <cuda_fp16.h>
#include <math.h>
#include <stdint.h>

// Problem constants
#define EN      200000
#define IND     128
#define HIDD    32
#define NH      4
#define OUTD    128
#define MAXK    16
#define TM      64                     // rows per block (attention kernel)
#define NBLK    (EN / TM)              // 3125
#define PTM     128                    // rows per tile (projection kernel)
#define PTILES  ((EN + PTM - 1) / PTM) // 1563
#define PGRID   148
#define SH      136                    // smem row stride in halfs (128 + 8 pad)

// Scratch (device globals; no allocation)
// NOTE: 128-half vectors stored PERMUTED: chunk c (16B) at pcol, see perm().
__device__ __half g_kv[(size_t)EN * 256];  // [e][0:128]=k(perm), [128:256]=v(perm)
__device__ __half g_q [(size_t)EN * 128];  // q, permuted
__device__ __half g_g [(size_t)EN * 128];  // sigmoid gate, permuted
__device__ float  g_bh[(size_t)EN * NH];   // [e][h]
__device__ int    g_kstride;               // 2 if klist is int64, 1 if int32

// permutation of a 128-half vector: half index cc -> stored index
// cc = h*32 + p*16 + c8*8 + jj   ->   c8*64 + (h*2+p)*8 + jj
__device__ __forceinline__ int perm(int cc)
{
    return (((cc >> 3) & 1) << 6) | (((cc >> 4) & 7) << 3) | (cc & 7);
}

// m16n8k16 f16 MMA, fp32 accum. A row-major frag, B col-major frag.
__device__ __forceinline__ void mma16816(float c[4], unsigned a0, unsigned a1,
                                         unsigned a2, unsigned a3,
                                         unsigned b0, unsigned b1)
{
    asm volatile(
        "mma.sync.aligned.m16n8k16.row.col.f32.f16.f16.f32 "
        "{%0,%1,%2,%3}, {%4,%5,%6,%7}, {%8,%9}, {%0,%1,%2,%3};\n"
        : "+f"(c[0]), "+f"(c[1]), "+f"(c[2]), "+f"(c[3])
        : "r"(a0), "r"(a1), "r"(a2), "r"(a3), "r"(b0), "r"(b1));
}

__device__ __forceinline__ unsigned ldh2(const __half* p) { return *(const unsigned*)p; }

// ---------------------------------------------------------------------------
// Kernel A: ALL projections. 148 persistent blocks, 512 threads, double-
// buffered 128-row Z tiles. All four weight matrices resident in smem.
// Outputs stored in PERMUTED layout (see perm()).
// ---------------------------------------------------------------------------
__global__ void __launch_bounds__(512, 1) kproj_all(
    const float* __restrict__ Z,
    const float* __restrict__ Wk,
    const float* __restrict__ Wv,
    const float* __restrict__ Wq,
    const float* __restrict__ Wg,
    const float* __restrict__ Wb,
    const float* __restrict__ bgv,
    const int*   __restrict__ kw)
{
    extern __shared__ __half sh[];
    __half* sZ0 = sh;                             // [128][SH]
    __half* sZ1 = sh + PTM * SH;                  // [128][SH]
    __half* sW  = sh + 2 * PTM * SH;              // [4][128][SH]
    __half* sWb = sh + 2 * PTM * SH + 4 * 128 * SH;  // [512]
    float*  sbg = (float*)(sWb + 512);            // [128]

    const int tid = threadIdx.x;

    if (blockIdx.x == 0 && tid == 0) {
        int is64 = 1;
        for (int i = 0; i < 4096; i++) {
            int hi = kw[2 * i + 1];
            if (hi != 0 && hi != -1) { is64 = 0; break; }
        }
        g_kstride = is64 ? 2 : 1;
    }

    // Stage all weights once
    const float* Wsrcs[4] = {Wk, Wv, Wq, Wg};
    #pragma unroll
    for (int c = 0; c < 4; c++) {
        const float* Wsrc = Wsrcs[c];
        __half* dst = sW + c * 128 * SH;
        for (int i = tid; i < 128 * 32; i += 512) {
            int col = i >> 5, kq = i & 31;
            float4 w = *(const float4*)(Wsrc + (size_t)col * IND + kq * 4);
            *(__half2*)&dst[col * SH + kq * 4]     = __floats2half2_rn(w.x, w.y);
            *(__half2*)&dst[col * SH + kq * 4 + 2] = __floats2half2_rn(w.z, w.w);
        }
    }
    for (int i = tid; i < NH * IND; i += 512) sWb[i] = __float2half_rn(Wb[i]);
    for (int i = tid; i < 128; i += 512) sbg[i] = bgv[i];

    const int lane = tid & 31, wid = tid >> 5;
    const int g = lane >> 2, tig = lane & 3;
    const int rb = (wid & 7) * 16;    // row band 0..112
    const int cb = (wid >> 3) * 64;   // col band 0,64

    // Tile loader (fp32 -> fp16), 128 rows
    auto load_tile = [&](int t, __half* dstZ) {
        const int row0 = t * PTM;
        for (int i = tid; i < PTM * 32; i += 512) {
            int r = i >> 5, c = i & 31;
            int rg = row0 + r; if (rg >= EN) rg = EN - 1;
            float4 v = *(const float4*)(Z + (size_t)rg * IND + c * 4);
            *(__half2*)&dstZ[r * SH + c * 4]     = __floats2half2_rn(v.x, v.y);
            *(__half2*)&dstZ[r * SH + c * 4 + 2] = __floats2half2_rn(v.z, v.w);
        }
    };

    int t = blockIdx.x;
    if (t < PTILES) load_tile(t, sZ0);
    __syncthreads();

    int buf = 0;
    for (; t < PTILES; t += PGRID) {
        __half* sZ = buf ? sZ1 : sZ0;
        __half* sZn = buf ? sZ0 : sZ1;

        // Prefetch next tile into the other buffer (overlaps with MMA below)
        int tn = t + PGRID;
        if (tn < PTILES) load_tile(tn, sZn);

        const int row0 = t * PTM;
        const int r0g = row0 + rb + g;

        #pragma unroll
        for (int chunk = 0; chunk < 4; chunk++) {
            const __half* Wc = sW + chunk * 128 * SH;
            float acc[8][4] = {};
            #pragma unroll
            for (int k0 = 0; k0 < 8; k0++) {
                const __half* pa = sZ + (rb + g) * SH + k0 * 16 + tig * 2;
                unsigned a0 = ldh2(pa);
                unsigned a1 = ldh2(pa + 8 * SH);
                unsigned a2 = ldh2(pa + 8);
                unsigned a3 = ldh2(pa + 8 * SH + 8);
                #pragma unroll
                for (int nt = 0; nt < 8; nt++) {
                    const __half* pb = Wc + (cb + nt * 8 + g) * SH + k0 * 16 + tig * 2;
                    mma16816(acc[nt], a0, a1, a2, a3, ldh2(pb), ldh2(pb + 8));
                }
            }

            if (chunk < 2) {
                #pragma unroll
                for (int nt = 0; nt < 8; nt++) {
                    int cc = cb + nt * 8 + tig * 2;            // within-part col
                    int col = chunk * 128 + perm(cc);          // permuted target
                    if (r0g < EN)
                        *(__half2*)&g_kv[(size_t)r0g * 256 + col] =
                            __floats2half2_rn(acc[nt][0], acc[nt][1]);
                    if (r0g + 8 < EN)
                        *(__half2*)&g_kv[(size_t)(r0g + 8) * 256 + col] =
                            __floats2half2_rn(acc[nt][2], acc[nt][3]);
                }
            } else if (chunk == 2) {
                #pragma unroll
                for (int nt = 0; nt < 8; nt++) {
                    int cc = cb + nt * 8 + tig * 2;
                    int col = perm(cc);
                    if (r0g < EN)
                        __stcs((__half2*)&g_q[(size_t)r0g * 128 + col],
                               __floats2half2_rn(acc[nt][0], acc[nt][1]));
                    if (r0g + 8 < EN)
                        __stcs((__half2*)&g_q[(size_t)(r0g + 8) * 128 + col],
                               __floats2half2_rn(acc[nt][2], acc[nt][3]));
                }
            } else {
                #pragma unroll
                for (int nt = 0; nt < 8; nt++) {
                    int cc = cb + nt * 8 + tig * 2;
                    int col = perm(cc);
                    float g0 = 1.f / (1.f + __expf(-(acc[nt][0] + sbg[cc])));
                    float g1 = 1.f / (1.f + __expf(-(acc[nt][1] + sbg[cc + 1])));
                    float g2 = 1.f / (1.f + __expf(-(acc[nt][2] + sbg[cc])));
                    float g3 = 1.f / (1.f + __expf(-(acc[nt][3] + sbg[cc + 1])));
                    if (r0g < EN)
                        __stcs((__half2*)&g_g[(size_t)r0g * 128 + col],
                               __floats2half2_rn(g0, g1));
                    if (r0g + 8 < EN)
                        __stcs((__half2*)&g_g[(size_t)(r0g + 8) * 128 + col],
                               __floats2half2_rn(g2, g3));
                }
            }
        }

        // b tail: 512 (row, head) dots, one per thread
        {
            int r = tid >> 2, h = tid & 3;
            int rg = row0 + r;
            if (rg < EN) {
                float s = 0.f;
                #pragma unroll 8
                for (int k = 0; k < 128; k += 2) {
                    float2 a = __half22float2(*(__half2*)&sZ[r * SH + k]);
                    float2 b = __half22float2(*(__half2*)&sWb[h * IND + k]);
                    s += a.x * b.x + a.y * b.y;
                }
                g_bh[(size_t)rg * NH + h] = s;
            }
        }

        __syncthreads();   // next-tile stores complete; current tile consumed
        buf ^= 1;
    }
}

// ---------------------------------------------------------------------------
// Kernel B: gather attention + gating + output GEMM. 512 threads, 64 rows.
// Thread PAIR per (row, head); permuted layout makes every gather LDG.128's
// 8-lane footprint cover exactly one 128B line. HFMA2 K-dot + V-accumulation
// (fp32 flush every 4 slots). Branch-free slot loop keeps shuffles converged.
// ---------------------------------------------------------------------------
__global__ void __launch_bounds__(512, 2) katt_out(
    const int*   __restrict__ kw,
    const float* __restrict__ Wout,
    const float* __restrict__ bout,
    float*       __restrict__ out)
{
    extern __shared__ __half sh[];
    __half* sX  = sh;                          // [64][SH]  gated X (A operand)
    __half* sW  = sh + 64 * SH;                // [128][SH] Wout (B operand)
    int*    skl = (int*)(sh + 192 * SH);       // [64][32]
    float*  sbo = (float*)(skl + 2048);        // [128]

    const int tid  = threadIdx.x;
    const int row0 = blockIdx.x * TM;
    const int st   = g_kstride;

    // Stage Wout + bout + klist
    const float4* W4 = (const float4*)Wout;
    for (int i = tid; i < 128 * 32; i += 512) {
        int o = i >> 5, kq = i & 31;
        float4 w = W4[o * 32 + kq];
        *(__half2*)&sW[o * SH + kq * 4]     = __floats2half2_rn(w.x, w.y);
        *(__half2*)&sW[o * SH + kq * 4 + 2] = __floats2half2_rn(w.z, w.w);
    }
    for (int i = tid; i < 128; i += 512) sbo[i] = bout[i];
    for (int i = tid; i < TM * 32; i += 512)
        skl[i] = kw[((size_t)row0 * 32 + i) * st];
    __syncthreads();

    // ---- Gather phase: thread pair per (row, head), permuted-line loads
    {
        const int p = tid & 1;            // 16-dim half selector
        const int h = (tid >> 1) & 3;     // head
        const int r = tid >> 3;           // row in tile
        const size_t e = (size_t)row0 + r;
        const int off = h * 32 + p * 16;  // TRUE column base (for sX write)
        const int grp = ((h << 1) | p) * 8;   // permuted chunk base (halfs)

        // q resident as half2 (permuted load, no conversion)
        __half2 q2[8];
        {
            uint4 u0 = __ldcs((const uint4*)&g_q[e * 128 + grp]);
            uint4 u1 = __ldcs((const uint4*)&g_q[e * 128 + 64 + grp]);
            const __half2* h0 = (const __half2*)&u0;
            const __half2* h1 = (const __half2*)&u1;
            #pragma unroll
            for (int pp = 0; pp < 4; pp++) { q2[pp] = h0[pp]; q2[4 + pp] = h1[pp]; }
        }

        const float scale = 0.17677669529663687f;   // 1/sqrt(32)
        float den = 0.f;
        float att[16];
        #pragma unroll
        for (int j = 0; j < 16; j++) att[j] = 0.f;

        #pragma unroll
        for (int sb = 0; sb < 4; sb++) {            // 4 groups of 4 slots
            int4 ii4 = *(const int4*)&skl[r * 32 + sb * 4];
            int4 jj4 = *(const int4*)&skl[r * 32 + 16 + sb * 4];
            int iis[4] = {ii4.x, ii4.y, ii4.z, ii4.w};
            int jjs[4] = {jj4.x, jj4.y, jj4.z, jj4.w};

            __half2 att2[8];                        // fp16 partial for this group
            #pragma unroll
            for (int pp = 0; pp < 8; pp++) att2[pp] = __floats2half2_rn(0.f, 0.f);

            #pragma unroll
            for (int s4 = 0; s4 < 4; s4++) {
                int ii_raw = iis[s4];
                bool valid = (ii_raw >= 0);
                int ii = valid ? min(ii_raw, EN - 1) : 0;
                int jj = min(max(jjs[s4], 0), EN - 1);

                const __half* kb = &g_kv[(size_t)ii * 256];
                uint4 uk0 = *(const uint4*)&kb[grp];        // line 1 across lanes
                uint4 uk1 = *(const uint4*)&kb[64 + grp];   // line 2
                __half2 d2 = __floats2half2_rn(0.f, 0.f);
                {
                    const __half2* h0 = (const __half2*)&uk0;
                    const __half2* h1 = (const __half2*)&uk1;
                    #pragma unroll
                    for (int pp = 0; pp < 4; pp++) d2 = __hfma2(q2[pp], h0[pp], d2);
                    #pragma unroll
                    for (int pp = 0; pp < 4; pp++) d2 = __hfma2(q2[4 + pp], h1[pp], d2);
                }
                float2 df = __half22float2(d2);
                float d = df.x + df.y;
                d += __shfl_xor_sync(0xFFFFFFFF, d, 1);   // pair reduction

                float w = valid ? __expf(scale * d + g_bh[(size_t)jj * NH + h]) : 0.f;
                den += valid ? w : 1.f;                   // exp(0) for masked slot
                __half2 w2 = __float2half2_rn(w);

                uint4 uv0 = *(const uint4*)&kb[128 + grp];
                uint4 uv1 = *(const uint4*)&kb[128 + 64 + grp];
                {
                    const __half2* v0 = (const __half2*)&uv0;
                    const __half2* v1 = (const __half2*)&uv1;
                    #pragma unroll
                    for (int pp = 0; pp < 4; pp++) att2[pp]     = __hfma2(w2, v0[pp], att2[pp]);
                    #pragma unroll
                    for (int pp = 0; pp < 4; pp++) att2[4 + pp] = __hfma2(w2, v1[pp], att2[4 + pp]);
                }
            }

            // flush fp16 partials to fp32
            #pragma unroll
            for (int pp = 0; pp < 8; pp++) {
                float2 f = __half22float2(att2[pp]);
                att[pp * 2]     += f.x;
                att[pp * 2 + 1] += f.y;
            }
        }

        // gate (permuted load) and write X at TRUE columns (A for out GEMM)
        const float inv = 1.f / den;
        uint4 ug0 = __ldcs((const uint4*)&g_g[e * 128 + grp]);
        uint4 ug1 = __ldcs((const uint4*)&g_g[e * 128 + 64 + grp]);
        const __half2* hg0 = (const __half2*)&ug0;
        const __half2* hg1 = (const __half2*)&ug1;
        #pragma unroll
        for (int pp = 0; pp < 4; pp++) {
            float2 f0 = __half22float2(hg0[pp]);
            float2 f1 = __half22float2(hg1[pp]);
            *(__half2*)&sX[r * SH + off + pp * 2] =
                __floats2half2_rn(f0.x * att[pp*2] * inv, f0.y * att[pp*2+1] * inv);
            *(__half2*)&sX[r * SH + off + 8 + pp * 2] =
                __floats2half2_rn(f1.x * att[8 + pp*2] * inv, f1.y * att[8 + pp*2+1] * inv);
        }
    }
    __syncthreads();

    // ---- Output GEMM: out = X @ Wout^T + bout. 16 warps: 4m x 4n.
    const int lane = tid & 31, wid = tid >> 5;
    const int g = lane >> 2, tig = lane & 3;
    const int rw = (wid & 3) * 16;      // row band
    const int cw = (wid >> 2) * 32;     // col band

    float acc[4][4] = {};
    #pragma unroll
    for (int k0 = 0; k0 < 8; k0++) {
        const __half* pa = sX + (rw + g) * SH + k0 * 16 + tig * 2;
        unsigned a0 = ldh2(pa);
        unsigned a1 = ldh2(pa + 8 * SH);
        unsigned a2 = ldh2(pa + 8);
        unsigned a3 = ldh2(pa + 8 * SH + 8);
        #pragma unroll
        for (int nt = 0; nt < 4; nt++) {
            const __half* pb = sW + (cw + nt * 8 + g) * SH + k0 * 16 + tig * 2;
            mma16816(acc[nt], a0, a1, a2, a3, ldh2(pb), ldh2(pb + 8));
        }
    }

    #pragma unroll
    for (int nt = 0; nt < 4; nt++) {
        int col = cw + nt * 8 + tig * 2;
        size_t e0 = (size_t)(row0 + rw + g);
        float2 o0 = make_float2(acc[nt][0] + sbo[col], acc[nt][1] + sbo[col + 1]);
        float2 o1 = make_float2(acc[nt][2] + sbo[col], acc[nt][3] + sbo[col + 1]);
        __stcs((float2*)&out[e0 * 128 + col], o0);
        __stcs((float2*)&out[(e0 + 8) * 128 + col], o1);
    }
}

// ---------------------------------------------------------------------------
extern "C" void kernel_launch(void* const* d_in, const int* in_sizes, int n_in,
                              void* d_out, int out_size)
{
    // Locate Z and klist by element count; remaining inputs keep dict order:
    // Wq, Wk, Wv, Wb, Wg, bg, Wout, bout
    const float* Z = nullptr;
    const int*   klist = nullptr;
    const void*  rest[16];
    int nrest = 0;
    for (int i = 0; i < n_in; i++) {
        if (in_sizes[i] == 25600000)      Z     = (const float*)d_in[i];
        else if (in_sizes[i] == 6400000)  klist = (const int*)d_in[i];
        else                              rest[nrest++] = d_in[i];
    }
    const float* Wq   = (const float*)rest[0];
    const float* Wk   = (const float*)rest[1];
    const float* Wv   = (const float*)rest[2];
    const float* Wb   = (const float*)rest[3];
    const float* Wg   = (const float*)rest[4];
    const float* bg   = (const float*)rest[5];
    const float* Wout = (const float*)rest[6];
    const float* bout = (const float*)rest[7];
    float* out = (float*)d_out;

    const int smemP = (2 * PTM * SH + 4 * 128 * SH + 512) * 2 + 128 * 4;  // 210,432 B
    const int smemB = 192 * SH * 2 + 2048 * 4 + 128 * 4;                  // 60,928 B

    cudaFuncSetAttribute(kproj_all, cudaFuncAttributeMaxDynamicSharedMemorySize, smemP);
    cudaFuncSetAttribute(katt_out,  cudaFuncAttributeMaxDynamicSharedMemorySize, smemB);

    kproj_all<<<PGRID, 512, smemP>>>(Z, Wk, Wv, Wq, Wg, Wb, bg, klist);
    katt_out <<<NBLK, 512, smemB>>>(klist, Wout, bout, out);
}